// round 17
// baseline (speedup 1.0000x reference)
#include <cuda_runtime.h>
#include <cstdint>

#define NBATCH 256
#define NN     64
#define DT     4096
#define THREADS 256

#define SLICE 512                       // t-columns per CTA
#define XST   520                       // floats; 520 % 32 == 8 -> conflict-free B LDS
#define WSTR  68
#define SMEM_FLOATS (NN * XST + NN * WSTR + NN + 8)
#define SMEM_BYTES  (SMEM_FLOATS * 4)   // 150816 B -> 1 CTA/SM

__device__ float        part_s [NBATCH][8][NN];
__device__ float        part_ss[NBATCH][8][NN];
__device__ unsigned int cnt[NBATCH];    // monotonic across graph replays

__device__ __forceinline__ uint32_t f2tf32(float f) {
    uint32_t r;
    asm("cvt.rna.tf32.f32 %0, %1;" : "=r"(r) : "f"(f));
    return r;
}
__device__ __forceinline__ void mma_tf32(float& c0, float& c1, float& c2, float& c3,
                                         uint32_t a0, uint32_t a1, uint32_t a2, uint32_t a3,
                                         uint32_t b0, uint32_t b1) {
    asm volatile(
        "mma.sync.aligned.m16n8k8.row.col.f32.tf32.tf32.f32 "
        "{%0,%1,%2,%3}, {%4,%5,%6,%7}, {%8,%9}, {%0,%1,%2,%3};"
        : "+f"(c0), "+f"(c1), "+f"(c2), "+f"(c3)
        : "r"(a0), "r"(a1), "r"(a2), "r"(a3), "r"(b0), "r"(b1));
}
__device__ __forceinline__ void cp_async16(void* smem_dst, const void* gsrc) {
    unsigned sa = (unsigned)__cvta_generic_to_shared(smem_dst);
    asm volatile("cp.async.cg.shared.global [%0], [%1], 16;" :: "r"(sa), "l"(gsrc));
}

// ============================================================================
// Single pass: 2048 CTAs = (batch, slice of 512 t). x is read ONCE.
//   A) cp.async the 64x512 slice into smem (128 KB)
//   B) per-slice partial variance sums -> global scratch
//   C) per-batch cross-CTA barrier (monotonic counter; replay-safe)
//   D) reduce partials (fixed order) -> e -> coefs -> softmax -> A-frags
//   E) tf32 GEMM + exact fp32 residual from the resident slice; no restaging
// ============================================================================
__global__ void __launch_bounds__(THREADS, 1)
dga_onepass(const float* __restrict__ x,  const float* __restrict__ wq,
            const float* __restrict__ bq, const float* __restrict__ wk,
            const float* __restrict__ bk, float* __restrict__ out,
            float* __restrict__ attn)
{
    extern __shared__ float smf[];
    float* xs   = smf;                    // [64][520]
    float* w_sm = smf + NN * XST;         // [64][68]
    float* e_sm = w_sm + NN * WSTR;       // [64]
    float* coef = e_sm + NN;              // [4]

    const int bid  = blockIdx.x;
    const int b    = bid >> 3;
    const int sl   = bid & 7;
    const int tid  = threadIdx.x;
    const int warp = tid >> 5;
    const int lane = tid & 31;
    const int tbase = sl * SLICE;
    const float* xb = x   + (size_t)b * NN * DT;
    float*       ob = out + (size_t)b * NN * DT;

    // ---- A: stage slice (8192 x 16B cp.async, fire-and-forget) ----
    #pragma unroll
    for (int s = 0; s < 32; ++s) {
        int u = tid + 256 * s;
        int j = u >> 7, q = u & 127;
        cp_async16(&xs[j * XST + q * 4], xb + (size_t)j * DT + tbase + q * 4);
    }
    asm volatile("cp.async.commit_group;");
    asm volatile("cp.async.wait_group 0;");
    __syncthreads();

    // ---- B: partial variance sums over this slice (8 rows per warp) ----
    #pragma unroll 1
    for (int r = 0; r < 8; ++r) {
        const int row = warp * 8 + r;
        float s = 0.f, ss = 0.f;
        #pragma unroll
        for (int k = 0; k < 4; ++k) {
            float4 v = *(const float4*)&xs[row * XST + (lane + 32 * k) * 4];
            s  += (v.x + v.y) + (v.z + v.w);
            ss += v.x * v.x + v.y * v.y + v.z * v.z + v.w * v.w;
        }
        #pragma unroll
        for (int m = 16; m; m >>= 1) {
            s  += __shfl_xor_sync(0xffffffffu, s,  m);
            ss += __shfl_xor_sync(0xffffffffu, ss, m);
        }
        if (lane == 0) {
            part_s [b][sl][row] = s;
            part_ss[b][sl][row] = ss;
        }
    }
    if (lane == 0) __threadfence();        // make this warp's partials visible
    __syncthreads();

    // ---- C: per-batch cross-CTA barrier (monotonic, no reset needed) ----
    if (tid == 0) {
        unsigned old = atomicAdd(&cnt[b], 1u);
        unsigned target = (old & ~7u) + 8u;   // this run's 8 arrivals
        unsigned v;
        do {
            asm volatile("ld.global.acquire.gpu.u32 %0, [%1];"
                         : "=r"(v) : "l"(&cnt[b]));
        } while (v < target);
    }
    __syncthreads();

    // ---- D: reduce partials (fixed order -> deterministic), softmax ----
    if (tid < NN) {
        float s = 0.f, ss = 0.f;
        #pragma unroll
        for (int p = 0; p < 8; ++p) {
            s  += part_s [b][p][tid];
            ss += part_ss[b][p][tid];
        }
        float mean = s * (1.0f / DT);
        e_sm[tid] = (ss - s * mean) * (1.0f / (DT - 1));
    }
    if (tid == 0) {
        float A = 0.f, B = 0.f, C = 0.f, Dc = 0.f;
        #pragma unroll
        for (int h = 0; h < 16; ++h) {
            float q = wq[h], qb = bq[h], k = wk[h], kb = bk[h];
            A += q * k; B += q * kb; C += qb * k; Dc += qb * kb;
        }
        coef[0] = A; coef[1] = B; coef[2] = C; coef[3] = Dc;
    }
    __syncthreads();
    {
        const int i  = tid >> 2;
        const int jg = tid & 3;
        const float ei = e_sm[i];
        const float m1 = 0.25f * (coef[0] * ei + coef[2]);   // SCALE = 0.25
        const float m0 = 0.25f * (coef[1] * ei + coef[3]);
        float sv[16];
        float mx = -3.4e38f;
        #pragma unroll
        for (int t = 0; t < 16; ++t) {
            int j = jg * 16 + t;
            float s = fmaf(m1, e_sm[j], m0);
            if (j == i) s = -1000000000.0f;
            sv[t] = s;
            mx = fmaxf(mx, s);
        }
        #pragma unroll
        for (int m = 1; m < 4; m <<= 1)
            mx = fmaxf(mx, __shfl_xor_sync(0xffffffffu, mx, m));
        float sum = 0.f;
        #pragma unroll
        for (int t = 0; t < 16; ++t) { sv[t] = __expf(sv[t] - mx); sum += sv[t]; }
        #pragma unroll
        for (int m = 1; m < 4; m <<= 1)
            sum += __shfl_xor_sync(0xffffffffu, sum, m);
        float inv = 1.0f / sum;

        float* arow = attn + (((size_t)b * NN) + i) * NN;
        #pragma unroll
        for (int t = 0; t < 16; ++t) {
            float w = sv[t] * inv;
            w_sm[i * WSTR + jg * 16 + t] = w;
            if (sl == 0) arow[jg * 16 + t] = w;   // one slice writes attn
        }
    }
    __syncthreads();

    // ---- A-fragments (W as tf32, rounded) in registers ----
    const int mw  = (warp & 3) * 16;       // warp's 16 output rows
    const int nco = (warp >> 2) * 32;      // warp's 32-t sub-slice per chunk
    const int g   = lane >> 2;
    const int tg  = lane & 3;

    uint32_t A[8][4];
    #pragma unroll
    for (int ks = 0; ks < 8; ++ks) {
        A[ks][0] = f2tf32(w_sm[(mw + g)     * WSTR + ks * 8 + tg]);
        A[ks][1] = f2tf32(w_sm[(mw + g + 8) * WSTR + ks * 8 + tg]);
        A[ks][2] = f2tf32(w_sm[(mw + g)     * WSTR + ks * 8 + tg + 4]);
        A[ks][3] = f2tf32(w_sm[(mw + g + 8) * WSTR + ks * 8 + tg + 4]);
    }

    // ---- E: GEMM over the resident slice; 8 chunks of 64 t; no barriers ----
    const uint32_t* xt = (const uint32_t*)xs;
    #pragma unroll 1
    for (int c = 0; c < 8; ++c) {
        const int cbase = c * 64;

        float C[4][4];
        #pragma unroll
        for (int t = 0; t < 4; ++t)
            C[t][0] = C[t][1] = C[t][2] = C[t][3] = 0.f;

        #pragma unroll
        for (int ks = 0; ks < 8; ++ks) {
            const uint32_t* b0r = &xt[(ks * 8 + tg)     * XST + cbase + nco + g];
            const uint32_t* b1r = &xt[(ks * 8 + tg + 4) * XST + cbase + nco + g];
            #pragma unroll
            for (int t = 0; t < 4; ++t) {
                uint32_t b0 = b0r[t * 8];             // single-phase LDS.32
                uint32_t b1 = b1r[t * 8];
                mma_tf32(C[t][0], C[t][1], C[t][2], C[t][3],
                         A[ks][0], A[ks][1], A[ks][2], A[ks][3], b0, b1);
            }
        }

        // epilogue: exact fp32 residual from the resident slice; stores
        #pragma unroll
        for (int t = 0; t < 4; ++t) {
            int lcol = cbase + nco + t * 8 + 2 * tg;
            float2 r0 = *(const float2*)&xs[(mw + g)     * XST + lcol];
            float2 r1 = *(const float2*)&xs[(mw + g + 8) * XST + lcol];
            *(float2*)(ob + (size_t)(mw + g)     * DT + tbase + lcol) =
                make_float2(C[t][0] + r0.x, C[t][1] + r0.y);
            *(float2*)(ob + (size_t)(mw + g + 8) * DT + tbase + lcol) =
                make_float2(C[t][2] + r1.x, C[t][3] + r1.y);
        }
    }
}

extern "C" void kernel_launch(void* const* d_in, const int* in_sizes, int n_in,
                              void* d_out, int out_size) {
    const float* x  = (const float*)d_in[0];
    const float* wq = (const float*)d_in[1];
    const float* bq = (const float*)d_in[2];
    const float* wk = (const float*)d_in[3];
    const float* bk = (const float*)d_in[4];
    float* out  = (float*)d_out;
    float* attn = out + (size_t)NBATCH * NN * DT;   // out tensor first, then attn

    cudaFuncSetAttribute(dga_onepass, cudaFuncAttributeMaxDynamicSharedMemorySize,
                         SMEM_BYTES);
    dga_onepass<<<NBATCH * 8, THREADS, SMEM_BYTES>>>(x, wq, bq, wk, bk, out, attn);
}